// round 5
// baseline (speedup 1.0000x reference)
#include <cuda_runtime.h>
#include <cstdint>

#define NLEVELS 12
#define HASH_MASK 0x7FFFFu
#define HASH_SIZE 524288
#define DIN 24
#define H1 32
#define H2 16
#define H3 8
#define P 2

// ---- constant weight bank layout (float offsets; all 16B-aligned) ----
#define W1OFF 0        // 24*32 transposed [i][o]
#define W2OFF 768      // 32*16 transposed
#define W3OFF 1280     // 16*8 transposed
#define W4OFF 1408     // 8
#define B1OFF 1416
#define B2OFF 1448
#define B3OFF 1464
#define B4OFF 1472
#define CW_TOTAL 1476

__constant__ __align__(16) float cw[CW_TOTAL];
__device__ __align__(16) float g_stage[CW_TOTAL];

// ---------- packed f32x2 helpers (sm_100+) ----------
__device__ __forceinline__ unsigned long long ffma2(unsigned long long a,
                                                    unsigned long long b,
                                                    unsigned long long c) {
    unsigned long long d;
    asm("fma.rn.f32x2 %0, %1, %2, %3;" : "=l"(d) : "l"(a), "l"(b), "l"(c));
    return d;
}
__device__ __forceinline__ unsigned long long pack2(float lo, float hi) {
    unsigned long long d;
    asm("mov.b64 %0, {%1, %2};" : "=l"(d) : "f"(lo), "f"(hi));
    return d;
}
__device__ __forceinline__ void unpack2(unsigned long long v, float& lo, float& hi) {
    asm("mov.b64 {%0, %1}, %2;" : "=f"(lo), "=f"(hi) : "l"(v));
}
// exact leaky-relu: max(v, 0.01v); FMNMX runs on the alu pipe
__device__ __forceinline__ float lrelu(float v) {
    return fmaxf(v, 0.01f * v);
}

// 16-byte constant fetch (compile-time offset -> uniform constant-port load)
__device__ __forceinline__ ulonglong2 cvec(int foff) {
    return *reinterpret_cast<const ulonglong2*>(cw + foff);
}

// ---- tiny staging kernel: transpose weights into pair-contiguous layout ----
__global__ void stage_weights(const float* __restrict__ W1, const float* __restrict__ b1,
                              const float* __restrict__ W2, const float* __restrict__ b2,
                              const float* __restrict__ W3, const float* __restrict__ b3,
                              const float* __restrict__ W4, const float* __restrict__ b4)
{
    const int t = threadIdx.x;
    for (int idx = t; idx < DIN * H1; idx += blockDim.x) {
        int i = idx >> 5, o = idx & 31;
        g_stage[W1OFF + idx] = W1[o * DIN + i];
    }
    for (int idx = t; idx < H1 * H2; idx += blockDim.x) {
        int i = idx >> 4, o = idx & 15;
        g_stage[W2OFF + idx] = W2[o * H1 + i];
    }
    for (int idx = t; idx < H2 * H3; idx += blockDim.x) {
        int i = idx >> 3, o = idx & 7;
        g_stage[W3OFF + idx] = W3[o * H2 + i];
    }
    if (t < H3) g_stage[W4OFF + t] = W4[t];
    if (t < H1) g_stage[B1OFF + t] = b1[t];
    if (t < H2) g_stage[B2OFF + t] = b2[t];
    if (t < H3) g_stage[B3OFF + t] = b3[t];
    if (t == 0) g_stage[B4OFF] = b4[0];
}

__global__ void __launch_bounds__(128, 6)
nhgrid_kernel(const float* __restrict__ x,
              const float* __restrict__ tables,
              float* __restrict__ out, int n)
{
    const int g = blockIdx.x * blockDim.x + threadIdx.x;
    const int p0 = 2 * g;
    if (p0 >= n) return;
    const bool has2 = (p0 + 1) < n;

    // ---- load 2 points (one float4) ----
    float xs0[P], xs1[P];
    if (has2) {
        const float4 v = __ldg(((const float4*)x) + g);
        xs0[0] = v.x; xs1[0] = v.y; xs0[1] = v.z; xs1[1] = v.w;
    } else {
        const float2 v = __ldg(((const float2*)x) + p0);
        xs0[0] = v.x; xs1[0] = v.y; xs0[1] = v.x; xs1[1] = v.y;
    }
    float c0[P], c1[P];
#pragma unroll
    for (int p = 0; p < P; p++) {
        c0[p] = xs0[p] * 0.5f + 0.5f;
        c1[p] = xs1[p] * 0.5f + 0.5f;
    }

    // spacings = 256.0 // 1.6**(L-1-i) in python float64 semantics
    const float sp[NLEVELS] = {1.f, 2.f, 3.f, 5.f, 9.f, 15.f,
                               24.f, 39.f, 62.f, 99.f, 159.f, 256.f};

    // ---------------- layer 1 accumulators (init with biases) ----------------
    unsigned long long a1[P][H1 / 2];
#pragma unroll
    for (int j = 0; j < H1 / 2; j++) {
        const unsigned long long b = pack2(cw[B1OFF + 2 * j], cw[B1OFF + 2 * j + 1]);
#pragma unroll
        for (int p = 0; p < P; p++) a1[p][j] = b;
    }

    // ---- gather+accumulate in 4 chunks of 3 levels (keeps f live-range small) ----
#pragma unroll
    for (int c = 0; c < 4; c++) {
        float2 ft[P][3];
#pragma unroll
        for (int l3 = 0; l3 < 3; l3++) {
            const int l = c * 3 + l3;
#pragma unroll
            for (int p = 0; p < P; p++) {
                const int d0 = (int)floorf(c0[p] * sp[l]);
                const int d1 = (int)floorf(c1[p] * sp[l]);
                const unsigned h = ((unsigned)d0 * 73856093u + (unsigned)d1 * 19349663u) & HASH_MASK;
                ft[p][l3] = __ldg(((const float2*)tables) + (size_t)l * HASH_SIZE + h);
            }
        }
#pragma unroll
        for (int l3 = 0; l3 < 3; l3++) {
            const int l = c * 3 + l3;
#pragma unroll
            for (int k = 0; k < 2; k++) {           // 2 feats per level; i = 2l+k
                const int i = 2 * l + k;
                unsigned long long ff[P];
#pragma unroll
                for (int p = 0; p < P; p++) {
                    const float fv = k ? ft[p][l3].y : ft[p][l3].x;
                    ff[p] = pack2(fv, fv);
                }
#pragma unroll
                for (int j = 0; j < H1 / 4; j++) {
                    const ulonglong2 ww = cvec(W1OFF + i * H1 + 4 * j);
#pragma unroll
                    for (int p = 0; p < P; p++) {
                        a1[p][2 * j]     = ffma2(ff[p], ww.x, a1[p][2 * j]);
                        a1[p][2 * j + 1] = ffma2(ff[p], ww.y, a1[p][2 * j + 1]);
                    }
                }
            }
        }
    }
    float y1[P][H1];
#pragma unroll
    for (int p = 0; p < P; p++)
#pragma unroll
        for (int j = 0; j < H1 / 2; j++) {
            float lo, hi;
            unpack2(a1[p][j], lo, hi);
            y1[p][2 * j]     = lrelu(lo);
            y1[p][2 * j + 1] = lrelu(hi);
        }

    // ---------------- layer 2: 32 -> 16, in two 8-output halves ----------------
    float y2[P][H2];
#pragma unroll
    for (int h = 0; h < 2; h++) {
        unsigned long long a2[P][4];                 // 8 outputs = 4 pairs
#pragma unroll
        for (int j = 0; j < 4; j++) {
            const unsigned long long b = pack2(cw[B2OFF + 8 * h + 2 * j],
                                               cw[B2OFF + 8 * h + 2 * j + 1]);
#pragma unroll
            for (int p = 0; p < P; p++) a2[p][j] = b;
        }
#pragma unroll
        for (int i = 0; i < H1; i++) {
            unsigned long long ff[P];
#pragma unroll
            for (int p = 0; p < P; p++) ff[p] = pack2(y1[p][i], y1[p][i]);
#pragma unroll
            for (int j = 0; j < 2; j++) {            // 2 cvecs cover 8 outputs
                const ulonglong2 ww = cvec(W2OFF + i * H2 + 8 * h + 4 * j);
#pragma unroll
                for (int p = 0; p < P; p++) {
                    a2[p][2 * j]     = ffma2(ff[p], ww.x, a2[p][2 * j]);
                    a2[p][2 * j + 1] = ffma2(ff[p], ww.y, a2[p][2 * j + 1]);
                }
            }
        }
#pragma unroll
        for (int p = 0; p < P; p++)
#pragma unroll
            for (int j = 0; j < 4; j++) {
                float lo, hi;
                unpack2(a2[p][j], lo, hi);
                y2[p][8 * h + 2 * j]     = lrelu(lo);
                y2[p][8 * h + 2 * j + 1] = lrelu(hi);
            }
    }

    // ---------------- layer 3: 16 -> 8 ----------------
    unsigned long long a3[P][H3 / 2];
#pragma unroll
    for (int j = 0; j < H3 / 2; j++) {
        const unsigned long long b = pack2(cw[B3OFF + 2 * j], cw[B3OFF + 2 * j + 1]);
#pragma unroll
        for (int p = 0; p < P; p++) a3[p][j] = b;
    }
#pragma unroll
    for (int i = 0; i < H2; i++) {
        unsigned long long ff[P];
#pragma unroll
        for (int p = 0; p < P; p++) ff[p] = pack2(y2[p][i], y2[p][i]);
#pragma unroll
        for (int j = 0; j < H3 / 4; j++) {
            const ulonglong2 ww = cvec(W3OFF + i * H3 + 4 * j);
#pragma unroll
            for (int p = 0; p < P; p++) {
                a3[p][2 * j]     = ffma2(ff[p], ww.x, a3[p][2 * j]);
                a3[p][2 * j + 1] = ffma2(ff[p], ww.y, a3[p][2 * j + 1]);
            }
        }
    }
    float y3[P][H3];
#pragma unroll
    for (int p = 0; p < P; p++)
#pragma unroll
        for (int j = 0; j < H3 / 2; j++) {
            float lo, hi;
            unpack2(a3[p][j], lo, hi);
            y3[p][2 * j]     = lrelu(lo);
            y3[p][2 * j + 1] = lrelu(hi);
        }

    // ---------------- layer 4: 8 -> 1, double LeakyReLU ----------------
    float z[P];
#pragma unroll
    for (int p = 0; p < P; p++) {
        float zz = cw[B4OFF];
#pragma unroll
        for (int i = 0; i < H3; i++)
            zz = fmaf(y3[p][i], cw[W4OFF + i], zz);
        zz = lrelu(zz);
        z[p] = lrelu(zz);
    }

    if (has2) {
        *reinterpret_cast<float2*>(out + p0) = make_float2(z[0], z[1]);
    } else {
        out[p0] = z[0];
    }
}

extern "C" void kernel_launch(void* const* d_in, const int* in_sizes, int n_in,
                              void* d_out, int out_size)
{
    const float* x      = (const float*)d_in[0];
    const float* tables = (const float*)d_in[1];
    const float* W1 = (const float*)d_in[2];
    const float* b1 = (const float*)d_in[3];
    const float* W2 = (const float*)d_in[4];
    const float* b2 = (const float*)d_in[5];
    const float* W3 = (const float*)d_in[6];
    const float* b3 = (const float*)d_in[7];
    const float* W4 = (const float*)d_in[8];
    const float* b4 = (const float*)d_in[9];
    float* out = (float*)d_out;

    const int n = in_sizes[0] / 2;   // x is [N, 2]

    stage_weights<<<1, 256>>>(W1, b1, W2, b2, W3, b3, W4, b4);

    void* stage_ptr = nullptr;
    cudaGetSymbolAddress(&stage_ptr, g_stage);
    cudaMemcpyToSymbolAsync(cw, stage_ptr, CW_TOTAL * sizeof(float), 0,
                            cudaMemcpyDeviceToDevice, 0);

    const int block = 128;
    const int pts_per_block = block * P;
    const int grid = (n + pts_per_block - 1) / pts_per_block;
    nhgrid_kernel<<<grid, block>>>(x, tables, out, n);
}

// round 7
// speedup vs baseline: 1.3332x; 1.3332x over previous
#include <cuda_runtime.h>
#include <cstdint>

#define NLEVELS 12
#define HASH_MASK 0x7FFFFu
#define HASH_SIZE 524288
#define DIN 24
#define H1 32
#define H2 16
#define H3 8
#define P 2

// ---- constant weight bank layout (float offsets; all 16B-aligned) ----
#define W1OFF 0        // 24*32 transposed [i][o]
#define W2OFF 768      // 32*16 transposed
#define W3OFF 1280     // 16*8 transposed
#define W4OFF 1408     // 8
#define B1OFF 1416
#define B2OFF 1448
#define B3OFF 1464
#define B4OFF 1472
#define CW_TOTAL 1476

__constant__ __align__(16) float cw[CW_TOTAL];
__device__ __align__(16) float g_stage[CW_TOTAL];

// ---------- packed f32x2 helpers (sm_100+) ----------
__device__ __forceinline__ unsigned long long ffma2(unsigned long long a,
                                                    unsigned long long b,
                                                    unsigned long long c) {
    unsigned long long d;
    asm("fma.rn.f32x2 %0, %1, %2, %3;" : "=l"(d) : "l"(a), "l"(b), "l"(c));
    return d;
}
__device__ __forceinline__ unsigned long long pack2(float lo, float hi) {
    unsigned long long d;
    asm("mov.b64 %0, {%1, %2};" : "=l"(d) : "f"(lo), "f"(hi));
    return d;
}
__device__ __forceinline__ void unpack2(unsigned long long v, float& lo, float& hi) {
    asm("mov.b64 {%0, %1}, %2;" : "=f"(lo), "=f"(hi) : "l"(v));
}
// exact leaky-relu: max(v, 0.01v) -> FMUL(fma pipe) + FMNMX(alu pipe)
__device__ __forceinline__ float lrelu(float v) {
    return fmaxf(v, 0.01f * v);
}

// 16-byte constant fetch (compile-time offset -> uniform constant-port load)
__device__ __forceinline__ ulonglong2 cvec(int foff) {
    return *reinterpret_cast<const ulonglong2*>(cw + foff);
}

// ---- tiny staging kernel: transpose weights into pair-contiguous layout ----
__global__ void stage_weights(const float* __restrict__ W1, const float* __restrict__ b1,
                              const float* __restrict__ W2, const float* __restrict__ b2,
                              const float* __restrict__ W3, const float* __restrict__ b3,
                              const float* __restrict__ W4, const float* __restrict__ b4)
{
    const int t = threadIdx.x;
    for (int idx = t; idx < DIN * H1; idx += blockDim.x) {
        int i = idx >> 5, o = idx & 31;
        g_stage[W1OFF + idx] = W1[o * DIN + i];
    }
    for (int idx = t; idx < H1 * H2; idx += blockDim.x) {
        int i = idx >> 4, o = idx & 15;
        g_stage[W2OFF + idx] = W2[o * H1 + i];
    }
    for (int idx = t; idx < H2 * H3; idx += blockDim.x) {
        int i = idx >> 3, o = idx & 7;
        g_stage[W3OFF + idx] = W3[o * H2 + i];
    }
    if (t < H3) g_stage[W4OFF + t] = W4[t];
    if (t < H1) g_stage[B1OFF + t] = b1[t];
    if (t < H2) g_stage[B2OFF + t] = b2[t];
    if (t < H3) g_stage[B3OFF + t] = b3[t];
    if (t == 0) g_stage[B4OFF] = b4[0];
}

__global__ void __launch_bounds__(128, 5)
nhgrid_kernel(const float* __restrict__ x,
              const float* __restrict__ tables,
              float* __restrict__ out, int n)
{
    const int g = blockIdx.x * blockDim.x + threadIdx.x;
    const int p0 = 2 * g;
    if (p0 >= n) return;
    const bool has2 = (p0 + 1) < n;

    // ---- load 2 points (one float4) ----
    float xs[P][2];
    if (has2) {
        const float4 v = __ldg(((const float4*)x) + g);
        xs[0][0] = v.x; xs[0][1] = v.y; xs[1][0] = v.z; xs[1][1] = v.w;
    } else {
        const float2 v = __ldg(((const float2*)x) + p0);
        xs[0][0] = v.x; xs[0][1] = v.y; xs[1][0] = v.x; xs[1][1] = v.y;
    }

    // spacings = 256.0 // 1.6**(L-1-i) in python float64 semantics
    const float sp[NLEVELS] = {1.f, 2.f, 3.f, 5.f, 9.f, 15.f,
                               24.f, 39.f, 62.f, 99.f, 159.f, 256.f};

    // ---- all hashes first, then all 24 gathers in flight (max MLP) ----
    unsigned hidx[P][NLEVELS];
#pragma unroll
    for (int p = 0; p < P; p++) {
        const float x0 = xs[p][0] * 0.5f + 0.5f;
        const float x1 = xs[p][1] * 0.5f + 0.5f;
#pragma unroll
        for (int l = 0; l < NLEVELS; l++) {
            const int d0 = (int)floorf(x0 * sp[l]);
            const int d1 = (int)floorf(x1 * sp[l]);
            hidx[p][l] = ((unsigned)d0 * 73856093u + (unsigned)d1 * 19349663u) & HASH_MASK;
        }
    }
    float f[P][DIN];
#pragma unroll
    for (int l = 0; l < NLEVELS; l++) {
#pragma unroll
        for (int p = 0; p < P; p++) {
            const float2 ft = __ldg(((const float2*)tables) + (size_t)l * HASH_SIZE + hidx[p][l]);
            f[p][2 * l]     = ft.x;
            f[p][2 * l + 1] = ft.y;
        }
    }

    // ---------------- layer 1: 24 -> 32 ----------------
    unsigned long long a1[P][H1 / 2];
#pragma unroll
    for (int j = 0; j < H1 / 2; j++) {
        const unsigned long long b = pack2(cw[B1OFF + 2 * j], cw[B1OFF + 2 * j + 1]);
#pragma unroll
        for (int p = 0; p < P; p++) a1[p][j] = b;
    }
#pragma unroll
    for (int i = 0; i < DIN; i++) {
        unsigned long long ff[P];
#pragma unroll
        for (int p = 0; p < P; p++) ff[p] = pack2(f[p][i], f[p][i]);
#pragma unroll
        for (int j = 0; j < H1 / 4; j++) {
            const ulonglong2 ww = cvec(W1OFF + i * H1 + 4 * j);
#pragma unroll
            for (int p = 0; p < P; p++) {
                a1[p][2 * j]     = ffma2(ff[p], ww.x, a1[p][2 * j]);
                a1[p][2 * j + 1] = ffma2(ff[p], ww.y, a1[p][2 * j + 1]);
            }
        }
    }
    float y1[P][H1];
#pragma unroll
    for (int p = 0; p < P; p++)
#pragma unroll
        for (int j = 0; j < H1 / 2; j++) {
            float lo, hi;
            unpack2(a1[p][j], lo, hi);
            y1[p][2 * j]     = lrelu(lo);
            y1[p][2 * j + 1] = lrelu(hi);
        }

    // ---------------- layer 2: 32 -> 16 ----------------
    unsigned long long a2[P][H2 / 2];
#pragma unroll
    for (int j = 0; j < H2 / 2; j++) {
        const unsigned long long b = pack2(cw[B2OFF + 2 * j], cw[B2OFF + 2 * j + 1]);
#pragma unroll
        for (int p = 0; p < P; p++) a2[p][j] = b;
    }
#pragma unroll
    for (int i = 0; i < H1; i++) {
        unsigned long long ff[P];
#pragma unroll
        for (int p = 0; p < P; p++) ff[p] = pack2(y1[p][i], y1[p][i]);
#pragma unroll
        for (int j = 0; j < H2 / 4; j++) {
            const ulonglong2 ww = cvec(W2OFF + i * H2 + 4 * j);
#pragma unroll
            for (int p = 0; p < P; p++) {
                a2[p][2 * j]     = ffma2(ff[p], ww.x, a2[p][2 * j]);
                a2[p][2 * j + 1] = ffma2(ff[p], ww.y, a2[p][2 * j + 1]);
            }
        }
    }
    float y2[P][H2];
#pragma unroll
    for (int p = 0; p < P; p++)
#pragma unroll
        for (int j = 0; j < H2 / 2; j++) {
            float lo, hi;
            unpack2(a2[p][j], lo, hi);
            y2[p][2 * j]     = lrelu(lo);
            y2[p][2 * j + 1] = lrelu(hi);
        }

    // ---------------- layer 3: 16 -> 8 ----------------
    unsigned long long a3[P][H3 / 2];
#pragma unroll
    for (int j = 0; j < H3 / 2; j++) {
        const unsigned long long b = pack2(cw[B3OFF + 2 * j], cw[B3OFF + 2 * j + 1]);
#pragma unroll
        for (int p = 0; p < P; p++) a3[p][j] = b;
    }
#pragma unroll
    for (int i = 0; i < H2; i++) {
        unsigned long long ff[P];
#pragma unroll
        for (int p = 0; p < P; p++) ff[p] = pack2(y2[p][i], y2[p][i]);
#pragma unroll
        for (int j = 0; j < H3 / 4; j++) {
            const ulonglong2 ww = cvec(W3OFF + i * H3 + 4 * j);
#pragma unroll
            for (int p = 0; p < P; p++) {
                a3[p][2 * j]     = ffma2(ff[p], ww.x, a3[p][2 * j]);
                a3[p][2 * j + 1] = ffma2(ff[p], ww.y, a3[p][2 * j + 1]);
            }
        }
    }
    float y3[P][H3];
#pragma unroll
    for (int p = 0; p < P; p++)
#pragma unroll
        for (int j = 0; j < H3 / 2; j++) {
            float lo, hi;
            unpack2(a3[p][j], lo, hi);
            y3[p][2 * j]     = lrelu(lo);
            y3[p][2 * j + 1] = lrelu(hi);
        }

    // ---------------- layer 4: 8 -> 1, double LeakyReLU ----------------
    float z[P];
#pragma unroll
    for (int p = 0; p < P; p++) {
        float zz = cw[B4OFF];
#pragma unroll
        for (int i = 0; i < H3; i++)
            zz = fmaf(y3[p][i], cw[W4OFF + i], zz);
        zz = lrelu(zz);
        z[p] = lrelu(zz);
    }

    if (has2) {
        *reinterpret_cast<float2*>(out + p0) = make_float2(z[0], z[1]);
    } else {
        out[p0] = z[0];
    }
}

extern "C" void kernel_launch(void* const* d_in, const int* in_sizes, int n_in,
                              void* d_out, int out_size)
{
    const float* x      = (const float*)d_in[0];
    const float* tables = (const float*)d_in[1];
    const float* W1 = (const float*)d_in[2];
    const float* b1 = (const float*)d_in[3];
    const float* W2 = (const float*)d_in[4];
    const float* b2 = (const float*)d_in[5];
    const float* W3 = (const float*)d_in[6];
    const float* b3 = (const float*)d_in[7];
    const float* W4 = (const float*)d_in[8];
    const float* b4 = (const float*)d_in[9];
    float* out = (float*)d_out;

    const int n = in_sizes[0] / 2;   // x is [N, 2]

    stage_weights<<<1, 256>>>(W1, b1, W2, b2, W3, b3, W4, b4);

    void* stage_ptr = nullptr;
    cudaGetSymbolAddress(&stage_ptr, g_stage);
    cudaMemcpyToSymbolAsync(cw, stage_ptr, CW_TOTAL * sizeof(float), 0,
                            cudaMemcpyDeviceToDevice, 0);

    const int block = 128;
    const int pts_per_block = block * P;
    const int grid = (n + pts_per_block - 1) / pts_per_block;
    nhgrid_kernel<<<grid, block>>>(x, tables, out, n);
}